// round 14
// baseline (speedup 1.0000x reference)
#include <cuda_runtime.h>
#include <cuda_bf16.h>

#define MAX_N  50000
#define MAXDEG 128
#define D      64
#define DIN    128
#define NEG_SLOPE 0.01f
#define BM     128          // rows per GEMM block
#define KC     32           // k-chunk

// Scratch (static __device__ arrays: allocation-free per harness rules)
__device__ __align__(16) float g_z[MAX_N * D];      // z_dst = h0 @ W_dst
__device__ float g_ssrc[MAX_N];
__device__ float g_sdst[MAX_N];
__device__ int   g_cnt[MAX_N];                       // in-degree (atomic cursor)
__device__ int   g_ebuf[MAX_N * MAXDEG];             // src idx slots per dst

// ---------------------------------------------------------------------------
__global__ void k_init(int N) {
    int i = blockIdx.x * blockDim.x + threadIdx.x;
    if (i < N) g_cnt[i] = 0;
}

// ---------------------------------------------------------------------------
// Register-blocked GEMM + fused edge-bucket fill.
// GEMM: z[N,64] = h0[N,128] @ W[128,64]; thread = 8 rows x 8 cols.
// Epilogue: s_dst from acc; s_src per-thread from h1.
// Tail: grid-stride direct-slot bucketing (overlaps LSU/atomics with other
// blocks' FFMA phase).
// ---------------------------------------------------------------------------
__global__ void __launch_bounds__(128) k_gemm(
        const float* __restrict__ h0,
        const float* __restrict__ h1,
        const float* __restrict__ W,
        const float* __restrict__ aw,
        const int* __restrict__ srcp,
        const int* __restrict__ dstp,
        int N, int E) {
    __shared__ float sW[DIN * D];      // 32 KB, [k][n]
    __shared__ float sA[BM * KC];      // 16 KB, [row][k^swz]

    int tid  = threadIdx.x;            // 0..127
    int row0 = blockIdx.x * BM;

    // Stage W once: 8192 floats = 2048 float4, 16/thread, coalesced
    {
        const float4* W4 = (const float4*)W;
        float4* sW4 = (float4*)sW;
        #pragma unroll
        for (int i = 0; i < 16; i++)
            sW4[tid + i * 128] = W4[tid + i * 128];
    }

    int rg = tid >> 3;                 // 0..15: row group (8 rows)
    int c0 = (tid & 7) * 8;            // 0..56: col group (8 cols)
    int q8 = (rg & 3) * 8;             // swizzle for this thread's rows

    float acc[64];
    #pragma unroll
    for (int i = 0; i < 64; i++) acc[i] = 0.0f;

    int myrow = row0 + tid;            // staging / s_src row for this thread

    for (int kc = 0; kc < DIN; kc += KC) {
        __syncthreads();
        // Stage A chunk: thread t handles row t, swizzled float4 stores
        {
            int tq8 = ((tid >> 3) & 3) * 8;
            float* sArow = &sA[tid * KC];
            if (myrow < N) {
                const float4* hp = (const float4*)(h0 + (size_t)myrow * DIN + kc);
                #pragma unroll
                for (int j = 0; j < 8; j++) {
                    float4 v = hp[j];
                    *(float4*)&sArow[(4 * j) ^ tq8] = v;
                }
            } else {
                #pragma unroll
                for (int j = 0; j < 8; j++)
                    *(float4*)&sArow[(4 * j) ^ tq8] = make_float4(0.f, 0.f, 0.f, 0.f);
            }
        }
        __syncthreads();

        const float* wbase = &sW[(size_t)kc * D + c0];
        #pragma unroll 4
        for (int k = 0; k < KC; k++) {
            int ks = k ^ q8;           // swizzled column
            float a[8];
            #pragma unroll
            for (int i = 0; i < 8; i++)
                a[i] = sA[(rg * 8 + i) * KC + ks];
            float4 w0 = *(const float4*)&wbase[k * D];
            float4 w1 = *(const float4*)&wbase[k * D + 4];
            #pragma unroll
            for (int i = 0; i < 8; i++) {
                acc[i * 8 + 0] += a[i] * w0.x;
                acc[i * 8 + 1] += a[i] * w0.y;
                acc[i * 8 + 2] += a[i] * w0.z;
                acc[i * 8 + 3] += a[i] * w0.w;
                acc[i * 8 + 4] += a[i] * w1.x;
                acc[i * 8 + 5] += a[i] * w1.y;
                acc[i * 8 + 6] += a[i] * w1.z;
                acc[i * 8 + 7] += a[i] * w1.w;
            }
        }
    }

    // Write z + s_dst partials
    float pd[8];
    #pragma unroll
    for (int i = 0; i < 8; i++) {
        int row = row0 + rg * 8 + i;
        pd[i] = 0.0f;
        #pragma unroll
        for (int j = 0; j < 8; j++)
            pd[i] += acc[i * 8 + j] * __ldg(&aw[64 + c0 + j]);
        if (row < N) {
            float* zp = &g_z[(size_t)row * D + c0];
            *(float4*)zp       = make_float4(acc[i*8+0], acc[i*8+1], acc[i*8+2], acc[i*8+3]);
            *(float4*)(zp + 4) = make_float4(acc[i*8+4], acc[i*8+5], acc[i*8+6], acc[i*8+7]);
        }
    }
    // reduce pd over the 8 col-threads
    #pragma unroll
    for (int o = 1; o < 8; o <<= 1) {
        #pragma unroll
        for (int i = 0; i < 8; i++)
            pd[i] += __shfl_xor_sync(0xffffffffu, pd[i], o);
    }
    if ((tid & 7) == 0) {
        #pragma unroll
        for (int i = 0; i < 8; i++) {
            int row = row0 + rg * 8 + i;
            if (row < N) g_sdst[row] = pd[i];
        }
    }

    // s_src: per-thread full row dot (thread <-> row)
    if (myrow < N) {
        const float4* hp = (const float4*)(h1 + (size_t)myrow * D);
        float ps = 0.0f;
        #pragma unroll
        for (int j = 0; j < 16; j++) {
            float4 v = hp[j];
            ps += v.x * __ldg(&aw[4 * j])     + v.y * __ldg(&aw[4 * j + 1])
                + v.z * __ldg(&aw[4 * j + 2]) + v.w * __ldg(&aw[4 * j + 3]);
        }
        g_ssrc[myrow] = ps;
    }

    // Fused fill: grid-stride direct-slot bucketing (no extra launch;
    // overlaps with other blocks' FFMA phases)
    {
        int gid   = blockIdx.x * 128 + tid;
        int total = gridDim.x * 128;
        for (int e = gid; e < E; e += total) {
            int d = __ldg(&dstp[e]);
            int p = atomicAdd(&g_cnt[d], 1);
            if (p < MAXDEG) g_ebuf[(size_t)d * MAXDEG + p] = __ldg(&srcp[e]);
        }
    }
}

// ---------------------------------------------------------------------------
// Fused edge-softmax + aggregation + final. One warp per dst node.
//   out = z/deg + (sum_e ex_e * h1[src_e]) / (sum_e ex_e)
// Pair-edge float4 gather: lanes 0-15 gather edge j's row (float4 each),
// lanes 16-31 edge j+1. Halves combined via shfl_xor(…,16) at the end.
// ---------------------------------------------------------------------------
__global__ void k_agg2(const float* __restrict__ h1,
                       float* __restrict__ out, int N) {
    int node = blockIdx.x * (blockDim.x >> 5) + (threadIdx.x >> 5);
    int lane = threadIdx.x & 31;
    if (node >= N) return;

    int l16  = lane & 15;
    int half = lane >> 4;
    float4* op = (float4*)(out + (size_t)node * D);   // 16 x float4

    int n = g_cnt[node];
    if (n > MAXDEG) n = MAXDEG;
    if (n == 0) {                      // DGL semantics: zero for 0-in-degree
        if (half == 0) op[l16] = make_float4(0.f, 0.f, 0.f, 0.f);
        return;
    }

    float sd = g_sdst[node];
    const int* eb = &g_ebuf[(size_t)node * MAXDEG];
    float sumlane = 0.0f, ax = 0.0f, ay = 0.0f, az = 0.0f, aq = 0.0f;

    for (int c = 0; c < n; c += 32) {
        int m = n - c; if (m > 32) m = 32;

        // Phase 1: lane-parallel index load + score + exp
        int   idx = 0;
        float ex  = 0.0f;
        if (lane < m) {
            idx = eb[c + lane];
            float x = g_ssrc[idx] + sd;
            x = (x > 0.0f) ? x : NEG_SLOPE * x;
            ex = __expf(x);
        }
        sumlane += ex;

        // Phase 2: two edges per iteration; LDG.128 per lane.
        // m odd: jj=m <= 31 holds ex=0/idx=0 -> contributes nothing.
        #pragma unroll 4
        for (int j = 0; j < m; j += 2) {
            int   jj = j + half;
            int   s  = __shfl_sync(0xffffffffu, idx, jj);
            float e  = __shfl_sync(0xffffffffu, ex,  jj);
            float4 h = *((const float4*)(h1 + (size_t)s * D) + l16);
            ax += e * h.x; ay += e * h.y; az += e * h.z; aq += e * h.w;
        }
    }

    // combine the two edge-halves (same columns, disjoint edge subsets)
    ax += __shfl_xor_sync(0xffffffffu, ax, 16);
    ay += __shfl_xor_sync(0xffffffffu, ay, 16);
    az += __shfl_xor_sync(0xffffffffu, az, 16);
    aq += __shfl_xor_sync(0xffffffffu, aq, 16);

    float sum = sumlane;
    #pragma unroll
    for (int o = 16; o > 0; o >>= 1)
        sum += __shfl_xor_sync(0xffffffffu, sum, o);

    if (half == 0) {
        float inv  = __fdividef(1.0f, sum);
        float invn = __fdividef(1.0f, (float)n);
        float4 z = ((const float4*)(g_z + (size_t)node * D))[l16];
        op[l16] = make_float4(z.x * invn + ax * inv,
                              z.y * invn + ay * inv,
                              z.z * invn + az * inv,
                              z.w * invn + aq * inv);
    }
}

// ---------------------------------------------------------------------------
extern "C" void kernel_launch(void* const* d_in, const int* in_sizes, int n_in,
                              void* d_out, int out_size) {
    const float* h0 = (const float*)d_in[0];
    const float* h1 = (const float*)d_in[1];
    const float* W  = (const float*)d_in[2];
    const float* aw = (const float*)d_in[3];
    const int*   src = (const int*)d_in[4];
    const int*   dst = (const int*)d_in[5];
    float* out = (float*)d_out;

    int N = in_sizes[0] / DIN;
    int E = in_sizes[4];

    k_init <<<(N + 255) / 256, 256>>>(N);
    k_gemm <<<(N + BM - 1) / BM, 128>>>(h0, h1, W, aw, src, dst, N, E);
    // One warp per node: 8 warps/block -> (N+7)/8 blocks
    k_agg2 <<<(N + 7) / 8, 256>>>(h1, out, N);
}

// round 17
// speedup vs baseline: 1.0209x; 1.0209x over previous
#include <cuda_runtime.h>
#include <cuda_bf16.h>

#define MAX_N  50000
#define MAXDEG 128
#define D      64
#define DIN    128
#define NEG_SLOPE 0.01f
#define BM     128          // rows per GEMM block
#define KC     32           // k-chunk

// Scratch (static __device__ arrays: allocation-free per harness rules)
__device__ __align__(16) float g_z[MAX_N * D];      // z_dst = h0 @ W_dst
__device__ float g_ssrc[MAX_N];
__device__ float g_sdst[MAX_N];
__device__ int   g_cnt[MAX_N];                       // in-degree (atomic cursor)
__device__ int   g_ebuf[MAX_N * MAXDEG];             // src idx slots per dst

// ---------------------------------------------------------------------------
__global__ void k_init(int N) {
    int i = blockIdx.x * blockDim.x + threadIdx.x;
    if (i < N) g_cnt[i] = 0;
}

// ---------------------------------------------------------------------------
// Register-blocked GEMM: z[N,64] = h0[N,128] @ W[128,64]
// 128 threads/block, 128 rows/block. Thread = 8 rows x 8 cols (64-FMA tile).
// A staged in 4 chunks of k=32 (XOR-swizzled for conflict-free LDS).
// Epilogue: s_dst from acc; s_src per-thread from h1.
// ---------------------------------------------------------------------------
__global__ void __launch_bounds__(128) k_gemm(
        const float* __restrict__ h0,
        const float* __restrict__ h1,
        const float* __restrict__ W,
        const float* __restrict__ aw, int N) {
    __shared__ float sW[DIN * D];      // 32 KB, [k][n]
    __shared__ float sA[BM * KC];      // 16 KB, [row][k^swz]

    int tid  = threadIdx.x;            // 0..127
    int row0 = blockIdx.x * BM;

    // Stage W once: 8192 floats = 2048 float4, 16/thread, coalesced
    {
        const float4* W4 = (const float4*)W;
        float4* sW4 = (float4*)sW;
        #pragma unroll
        for (int i = 0; i < 16; i++)
            sW4[tid + i * 128] = W4[tid + i * 128];
    }

    int rg = tid >> 3;                 // 0..15: row group (8 rows)
    int c0 = (tid & 7) * 8;            // 0..56: col group (8 cols)
    int q8 = (rg & 3) * 8;             // swizzle for this thread's rows

    float acc[64];
    #pragma unroll
    for (int i = 0; i < 64; i++) acc[i] = 0.0f;

    int myrow = row0 + tid;            // staging / s_src row for this thread

    for (int kc = 0; kc < DIN; kc += KC) {
        __syncthreads();
        // Stage A chunk: thread t handles row t, swizzled float4 stores
        {
            int tq8 = ((tid >> 3) & 3) * 8;
            float* sArow = &sA[tid * KC];
            if (myrow < N) {
                const float4* hp = (const float4*)(h0 + (size_t)myrow * DIN + kc);
                #pragma unroll
                for (int j = 0; j < 8; j++) {
                    float4 v = hp[j];
                    *(float4*)&sArow[(4 * j) ^ tq8] = v;
                }
            } else {
                #pragma unroll
                for (int j = 0; j < 8; j++)
                    *(float4*)&sArow[(4 * j) ^ tq8] = make_float4(0.f, 0.f, 0.f, 0.f);
            }
        }
        __syncthreads();

        const float* wbase = &sW[(size_t)kc * D + c0];
        #pragma unroll 4
        for (int k = 0; k < KC; k++) {
            int ks = k ^ q8;           // swizzled column
            float a[8];
            #pragma unroll
            for (int i = 0; i < 8; i++)
                a[i] = sA[(rg * 8 + i) * KC + ks];
            float4 w0 = *(const float4*)&wbase[k * D];
            float4 w1 = *(const float4*)&wbase[k * D + 4];
            #pragma unroll
            for (int i = 0; i < 8; i++) {
                acc[i * 8 + 0] += a[i] * w0.x;
                acc[i * 8 + 1] += a[i] * w0.y;
                acc[i * 8 + 2] += a[i] * w0.z;
                acc[i * 8 + 3] += a[i] * w0.w;
                acc[i * 8 + 4] += a[i] * w1.x;
                acc[i * 8 + 5] += a[i] * w1.y;
                acc[i * 8 + 6] += a[i] * w1.z;
                acc[i * 8 + 7] += a[i] * w1.w;
            }
        }
    }

    // Write z + s_dst partials
    float pd[8];
    #pragma unroll
    for (int i = 0; i < 8; i++) {
        int row = row0 + rg * 8 + i;
        pd[i] = 0.0f;
        #pragma unroll
        for (int j = 0; j < 8; j++)
            pd[i] += acc[i * 8 + j] * __ldg(&aw[64 + c0 + j]);
        if (row < N) {
            float* zp = &g_z[(size_t)row * D + c0];
            *(float4*)zp       = make_float4(acc[i*8+0], acc[i*8+1], acc[i*8+2], acc[i*8+3]);
            *(float4*)(zp + 4) = make_float4(acc[i*8+4], acc[i*8+5], acc[i*8+6], acc[i*8+7]);
        }
    }
    // reduce pd over the 8 col-threads
    #pragma unroll
    for (int o = 1; o < 8; o <<= 1) {
        #pragma unroll
        for (int i = 0; i < 8; i++)
            pd[i] += __shfl_xor_sync(0xffffffffu, pd[i], o);
    }
    if ((tid & 7) == 0) {
        #pragma unroll
        for (int i = 0; i < 8; i++) {
            int row = row0 + rg * 8 + i;
            if (row < N) g_sdst[row] = pd[i];
        }
    }

    // s_src: per-thread full row dot (thread <-> row)
    if (myrow < N) {
        const float4* hp = (const float4*)(h1 + (size_t)myrow * D);
        float ps = 0.0f;
        #pragma unroll
        for (int j = 0; j < 16; j++) {
            float4 v = hp[j];
            ps += v.x * __ldg(&aw[4 * j])     + v.y * __ldg(&aw[4 * j + 1])
                + v.z * __ldg(&aw[4 * j + 2]) + v.w * __ldg(&aw[4 * j + 3]);
        }
        g_ssrc[myrow] = ps;
    }
}

// ---------------------------------------------------------------------------
// Direct-slot bucketing, 4 edges/thread via int4 (standalone: R13 config).
// ---------------------------------------------------------------------------
__global__ void k_fill(const int* __restrict__ src,
                       const int* __restrict__ dst, int E) {
    int i4 = (blockIdx.x * blockDim.x + threadIdx.x) * 4;
    if (i4 + 3 < E) {
        int4 d = *(const int4*)(dst + i4);
        int4 s = *(const int4*)(src + i4);
        int p;
        p = atomicAdd(&g_cnt[d.x], 1); if (p < MAXDEG) g_ebuf[(size_t)d.x * MAXDEG + p] = s.x;
        p = atomicAdd(&g_cnt[d.y], 1); if (p < MAXDEG) g_ebuf[(size_t)d.y * MAXDEG + p] = s.y;
        p = atomicAdd(&g_cnt[d.z], 1); if (p < MAXDEG) g_ebuf[(size_t)d.z * MAXDEG + p] = s.z;
        p = atomicAdd(&g_cnt[d.w], 1); if (p < MAXDEG) g_ebuf[(size_t)d.w * MAXDEG + p] = s.w;
    } else {
        for (int e = i4; e < E; e++) {
            int d = __ldg(&dst[e]);
            int p = atomicAdd(&g_cnt[d], 1);
            if (p < MAXDEG) g_ebuf[(size_t)d * MAXDEG + p] = __ldg(&src[e]);
        }
    }
}

// ---------------------------------------------------------------------------
// Fused edge-softmax + aggregation + final. One warp per dst node.
//   out = z/deg + (sum_e ex_e * h1[src_e]) / (sum_e ex_e)
// Pair-edge float4 gather: lanes 0-15 gather edge j's row (float4 each),
// lanes 16-31 edge j+1. Halves combined via shfl_xor(…,16) at the end.
// ---------------------------------------------------------------------------
__global__ void k_agg2(const float* __restrict__ h1,
                       float* __restrict__ out, int N) {
    int node = blockIdx.x * (blockDim.x >> 5) + (threadIdx.x >> 5);
    int lane = threadIdx.x & 31;
    if (node >= N) return;

    int l16  = lane & 15;
    int half = lane >> 4;
    float4* op = (float4*)(out + (size_t)node * D);   // 16 x float4

    int n = g_cnt[node];
    if (n > MAXDEG) n = MAXDEG;
    if (n == 0) {                      // DGL semantics: zero for 0-in-degree
        if (half == 0) op[l16] = make_float4(0.f, 0.f, 0.f, 0.f);
        return;
    }

    float sd = g_sdst[node];
    const int* eb = &g_ebuf[(size_t)node * MAXDEG];
    float sumlane = 0.0f, ax = 0.0f, ay = 0.0f, az = 0.0f, aq = 0.0f;

    for (int c = 0; c < n; c += 32) {
        int m = n - c; if (m > 32) m = 32;

        // Phase 1: lane-parallel index load + score + exp
        int   idx = 0;
        float ex  = 0.0f;
        if (lane < m) {
            idx = eb[c + lane];
            float x = g_ssrc[idx] + sd;
            x = (x > 0.0f) ? x : NEG_SLOPE * x;
            ex = __expf(x);
        }
        sumlane += ex;

        // Phase 2: two edges per iteration; LDG.128 per lane.
        // m odd: jj=m <= 31 holds ex=0/idx=0 -> contributes nothing.
        #pragma unroll 4
        for (int j = 0; j < m; j += 2) {
            int   jj = j + half;
            int   s  = __shfl_sync(0xffffffffu, idx, jj);
            float e  = __shfl_sync(0xffffffffu, ex,  jj);
            float4 h = *((const float4*)(h1 + (size_t)s * D) + l16);
            ax += e * h.x; ay += e * h.y; az += e * h.z; aq += e * h.w;
        }
    }

    // combine the two edge-halves (same columns, disjoint edge subsets)
    ax += __shfl_xor_sync(0xffffffffu, ax, 16);
    ay += __shfl_xor_sync(0xffffffffu, ay, 16);
    az += __shfl_xor_sync(0xffffffffu, az, 16);
    aq += __shfl_xor_sync(0xffffffffu, aq, 16);

    float sum = sumlane;
    #pragma unroll
    for (int o = 16; o > 0; o >>= 1)
        sum += __shfl_xor_sync(0xffffffffu, sum, o);

    if (half == 0) {
        float inv  = __fdividef(1.0f, sum);
        float invn = __fdividef(1.0f, (float)n);
        float4 z = ((const float4*)(g_z + (size_t)node * D))[l16];
        op[l16] = make_float4(z.x * invn + ax * inv,
                              z.y * invn + ay * inv,
                              z.z * invn + az * inv,
                              z.w * invn + aq * inv);
    }
}

// ---------------------------------------------------------------------------
extern "C" void kernel_launch(void* const* d_in, const int* in_sizes, int n_in,
                              void* d_out, int out_size) {
    const float* h0 = (const float*)d_in[0];
    const float* h1 = (const float*)d_in[1];
    const float* W  = (const float*)d_in[2];
    const float* aw = (const float*)d_in[3];
    const int*   src = (const int*)d_in[4];
    const int*   dst = (const int*)d_in[5];
    float* out = (float*)d_out;

    int N = in_sizes[0] / DIN;
    int E = in_sizes[4];

    k_init <<<(N + 255) / 256, 256>>>(N);
    k_gemm <<<(N + BM - 1) / BM, 128>>>(h0, h1, W, aw, N);
    k_fill <<<((E + 3) / 4 + 255) / 256, 256>>>(src, dst, E);
    // One warp per node: 8 warps/block -> (N+7)/8 blocks
    k_agg2 <<<(N + 7) / 8, 256>>>(h1, out, N);
}